// round 5
// baseline (speedup 1.0000x reference)
#include <cuda_runtime.h>
#include <cuda_bf16.h>
#include <math_constants.h>
#include <cstdint>

#define B_  4
#define H_  16
#define S_  2048
#define DM  1024
#define DK  64
#define M_  (B_*S_)

// ---------------- scratch (device globals; no allocation allowed) ----------
__device__ __nv_bfloat16 g_Xhi[M_*DM], g_Xlo[M_*DM];   // split activations
__device__ __nv_bfloat16 g_Whi[4*DM*DM], g_Wlo[4*DM*DM];
__device__ __nv_bfloat16 g_Qhi[M_*DM], g_Qlo[M_*DM];   // head layout, pre-scaled
__device__ __nv_bfloat16 g_Khi[M_*DM], g_Klo[M_*DM];
__device__ __nv_bfloat16 g_Vhi[M_*DM], g_Vlo[M_*DM];
__device__ __nv_bfloat16 g_Ohi[M_*DM], g_Olo[M_*DM];   // attn out, merged layout

__device__ __forceinline__ uint32_t smem_u32(const void* p) {
    uint32_t a;
    asm("{ .reg .u64 t; cvta.to.shared.u64 t, %1; cvt.u32.u64 %0, t; }"
        : "=r"(a) : "l"(p));
    return a;
}
__device__ __forceinline__ void cp16(uint32_t dst, const void* src) {
    asm volatile("cp.async.cg.shared.global [%0], [%1], 16;"
        :: "r"(dst), "l"(src));
}
#define CP_COMMIT() asm volatile("cp.async.commit_group;" ::: "memory")
#define CP_WAIT(n)  asm volatile("cp.async.wait_group %0;" :: "n"(n) : "memory")

__device__ __forceinline__ void ldsm_x4(uint32_t r[4], uint32_t addr) {
    asm volatile("ldmatrix.sync.aligned.m8n8.x4.shared.b16 {%0,%1,%2,%3}, [%4];"
        : "=r"(r[0]), "=r"(r[1]), "=r"(r[2]), "=r"(r[3]) : "r"(addr));
}
__device__ __forceinline__ void ldsm_x2(uint32_t r[2], uint32_t addr) {
    asm volatile("ldmatrix.sync.aligned.m8n8.x2.shared.b16 {%0,%1}, [%2];"
        : "=r"(r[0]), "=r"(r[1]) : "r"(addr));
}
__device__ __forceinline__ void ldsm_x2t(uint32_t r[2], uint32_t addr) {
    asm volatile("ldmatrix.sync.aligned.m8n8.x2.trans.shared.b16 {%0,%1}, [%2];"
        : "=r"(r[0]), "=r"(r[1]) : "r"(addr));
}
__device__ __forceinline__ void mma16816(float d[4], const uint32_t a[4],
                                         const uint32_t b[2]) {
    asm volatile(
        "mma.sync.aligned.m16n8k16.row.col.f32.bf16.bf16.f32 "
        "{%0,%1,%2,%3}, {%4,%5,%6,%7}, {%8,%9}, {%0,%1,%2,%3};"
        : "+f"(d[0]), "+f"(d[1]), "+f"(d[2]), "+f"(d[3])
        : "r"(a[0]), "r"(a[1]), "r"(a[2]), "r"(a[3]), "r"(b[0]), "r"(b[1]));
}

__device__ __forceinline__ uint32_t pk_bf2(float x, float y) {
    __nv_bfloat162 h = __floats2bfloat162_rn(x, y);
    return *reinterpret_cast<uint32_t*>(&h);
}
__device__ __forceinline__ void split2(float x, float y,
                                       uint32_t& hi, uint32_t& lo) {
    __nv_bfloat162 h2 = __floats2bfloat162_rn(x, y);
    float2 hf = __bfloat1622float2(h2);
    __nv_bfloat162 l2 = __floats2bfloat162_rn(x - hf.x, y - hf.y);
    hi = *reinterpret_cast<uint32_t*>(&h2);
    lo = *reinterpret_cast<uint32_t*>(&l2);
}

// Fast exp2 on FMA pipe (no MUFU).
__device__ __forceinline__ float exp2fast(float x) {
    x = fmaxf(x, -126.0f);
    float z = x + 12582912.0f;
    int   k = __float_as_int(z) - 0x4B400000;
    float f = x - (z - 12582912.0f);
    float p = fmaf(0.00133336f, f, 0.00961813f);
    p = fmaf(p, f, 0.05550411f);
    p = fmaf(p, f, 0.24022651f);
    p = fmaf(p, f, 0.69314718f);
    p = fmaf(p, f, 1.0f);
    return __int_as_float(__float_as_int(p) + (k << 23));
}

// ---------------------------------------------------------------------------
// fp32 -> bf16 hi/lo split
// ---------------------------------------------------------------------------
__global__ __launch_bounds__(256)
void split_bf16(const float* __restrict__ x,
                __nv_bfloat16* __restrict__ hi,
                __nv_bfloat16* __restrict__ lo, int n4)
{
    int i = blockIdx.x * blockDim.x + threadIdx.x;
    if (i >= n4) return;
    float4 v = reinterpret_cast<const float4*>(x)[i];
    uint32_t h0, l0, h1, l1;
    split2(v.x, v.y, h0, l0);
    split2(v.z, v.w, h1, l1);
    reinterpret_cast<uint2*>(hi)[i] = make_uint2(h0, h1);
    reinterpret_cast<uint2*>(lo)[i] = make_uint2(l0, l1);
}

// ---------------------------------------------------------------------------
// bf16 GEMM, cp.async 4-stage pipeline: out = A*W^T (+bias) (*scale)
//   3-pass fp32 emulation: Ahi*Whi + Alo*Whi + Ahi*Wlo
// mode 1: write hi/lo bf16 split-heads; mode 0: fp32 plain.
// ---------------------------------------------------------------------------
#define GTSTR  80
#define GTILE  (128*GTSTR)         // 10240
#define GSTAGE (4*GTILE)           // 40960: [AHI][ALO][WHI][WLO]
#define GEMM_SMEM (4*GSTAGE)       // 163840

__device__ __forceinline__ void gemm_issue(
    int c, uint32_t sb, int row, int gc,
    const __nv_bfloat16* Ahi, const __nv_bfloat16* Alo,
    const __nv_bfloat16* Whi, const __nv_bfloat16* Wlo,
    size_t aoff, size_t woff)
{
    if (c < DM / 32) {
        uint32_t st = sb + (c & 3) * GSTAGE + row * GTSTR + gc * 16;
        const size_t ae = aoff + c * 32 + gc * 8;
        const size_t we = woff + c * 32 + gc * 8;
        cp16(st,                Ahi + ae); cp16(st + 16,             Ahi + ae + 8);
        cp16(st +   GTILE,      Alo + ae); cp16(st +   GTILE + 16,   Alo + ae + 8);
        cp16(st + 2*GTILE,      Whi + we); cp16(st + 2*GTILE + 16,   Whi + we + 8);
        cp16(st + 3*GTILE,      Wlo + we); cp16(st + 3*GTILE + 16,   Wlo + we + 8);
    }
    CP_COMMIT();
}

extern __shared__ char dynsm[];

__global__ __launch_bounds__(256, 1)
void gemm_bf16(const __nv_bfloat16* __restrict__ Ahi,
               const __nv_bfloat16* __restrict__ Alo,
               const __nv_bfloat16* __restrict__ Whi,
               const __nv_bfloat16* __restrict__ Wlo,
               const float* __restrict__ bias, float scale,
               __nv_bfloat16* __restrict__ outhi,
               __nv_bfloat16* __restrict__ outlo,
               float* __restrict__ outf, int mode)
{
    const uint32_t sb = smem_u32(dynsm);
    const int tid = threadIdx.x;
    const int m0  = blockIdx.y << 7;
    const int n0  = blockIdx.x << 7;
    const int warp = tid >> 5;
    const int lane = tid & 31;
    const int wm = (warp >> 2) * 64;
    const int wn = (warp & 3) * 32;

    const uint32_t arow = (lane & 15) * GTSTR + (lane >> 4) * 16;
    const uint32_t brow = (lane & 7) * GTSTR + ((lane >> 3) & 1) * 16;

    const int lrow = tid >> 1;
    const int lgc  = (tid & 1) * 2;      // granule-pair base (0 / 2)
    const size_t aoff = (size_t)(m0 + lrow) * DM;
    const size_t woff = (size_t)(n0 + lrow) * DM;

    float acc[4][4][4];
    #pragma unroll
    for (int i = 0; i < 4; i++)
        #pragma unroll
        for (int j = 0; j < 4; j++)
            #pragma unroll
            for (int r = 0; r < 4; r++) acc[i][j][r] = 0.f;

    gemm_issue(0, sb, lrow, lgc, Ahi, Alo, Whi, Wlo, aoff, woff);
    gemm_issue(1, sb, lrow, lgc, Ahi, Alo, Whi, Wlo, aoff, woff);
    gemm_issue(2, sb, lrow, lgc, Ahi, Alo, Whi, Wlo, aoff, woff);

    for (int c = 0; c < DM / 32; ++c) {
        CP_WAIT(2);            // chunk c complete (per-thread)
        __syncthreads();       // cross-thread visibility; all done compute(c-1)
        gemm_issue(c + 3, sb, lrow, lgc, Ahi, Alo, Whi, Wlo, aoff, woff);

        const uint32_t st = sb + (c & 3) * GSTAGE;
        #pragma unroll
        for (int pass = 0; pass < 3; ++pass) {
            const uint32_t aoffs = st + ((pass == 1) ? GTILE : 0);
            const uint32_t boffs = st + ((pass == 2) ? 3*GTILE : 2*GTILE);
            #pragma unroll
            for (int ks = 0; ks < 2; ++ks) {
                uint32_t af[4][4], bf[4][2];
                #pragma unroll
                for (int mt = 0; mt < 4; ++mt)
                    ldsm_x4(af[mt], aoffs + (wm + mt*16) * GTSTR + ks*32 + arow);
                #pragma unroll
                for (int nt = 0; nt < 4; ++nt)
                    ldsm_x2(bf[nt], boffs + (wn + nt*8) * GTSTR + ks*32 + brow);
                #pragma unroll
                for (int mt = 0; mt < 4; ++mt)
                    #pragma unroll
                    for (int nt = 0; nt < 4; ++nt)
                        mma16816(acc[mt][nt], af[mt], bf[nt]);
            }
        }
    }

    #pragma unroll
    for (int mt = 0; mt < 4; ++mt) {
        #pragma unroll
        for (int nt = 0; nt < 4; ++nt) {
            const int col = n0 + wn + nt*8 + (lane & 3) * 2;
            const float2 bv = *(const float2*)(bias + col);
            #pragma unroll
            for (int half = 0; half < 2; ++half) {
                const int row = m0 + wm + mt*16 + (lane >> 2) + half * 8;
                const float v0 = (acc[mt][nt][2*half]   + bv.x) * scale;
                const float v1 = (acc[mt][nt][2*half+1] + bv.y) * scale;
                if (mode) {   // split-heads hi/lo bf16
                    const int head = col >> 6;
                    const int bi = row >> 11, si = row & (S_ - 1);
                    const size_t idx =
                        (((size_t)(bi * H_ + head)) * S_ + si) * DK + (col & 63);
                    uint32_t h2, l2; split2(v0, v1, h2, l2);
                    *(uint32_t*)(outhi + idx) = h2;
                    *(uint32_t*)(outlo + idx) = l2;
                } else {
                    *(float2*)(outf + (size_t)row * DM + col) =
                        make_float2(v0, v1);
                }
            }
        }
    }
}

// ---------------------------------------------------------------------------
// Flash attention on pre-split bf16 Q/K/V.
// CTA: 128 threads, 64 q-rows (4 warps x 16 rows); 64-key tiles;
// 2-stage cp.async KV pipeline; Q fragments hoisted to registers.
// smem 90 KB -> 2 CTAs/SM (two sync domains overlap softmax with MMA).
// ---------------------------------------------------------------------------
#define ASTR    144
#define QHI     0
#define QLO     9216
#define QSZ     18432
#define AK_HI   0
#define AK_LO   9216
#define AV_HI   18432
#define AV_LO   27648
#define KVSTAGE 36864
#define ATTN_SMEM (QSZ + 2*KVSTAGE)    // 92160

__device__ __forceinline__ void attn_issue(
    int kt, uint32_t stb, int row, int g0,
    const __nv_bfloat16* Khi, const __nv_bfloat16* Klo,
    const __nv_bfloat16* Vhi, const __nv_bfloat16* Vlo, size_t bh)
{
    if (kt < S_ / 64) {
        uint32_t st = stb + (kt & 1) * KVSTAGE + row * ASTR + g0 * 16;
        const size_t e = bh + (size_t)(kt * 64 + row) * DK + g0 * 8;
        #pragma unroll
        for (int j = 0; j < 4; j++) {
            cp16(st + AK_HI + j*16, Khi + e + j*8);
            cp16(st + AK_LO + j*16, Klo + e + j*8);
            cp16(st + AV_HI + j*16, Vhi + e + j*8);
            cp16(st + AV_LO + j*16, Vlo + e + j*8);
        }
    }
    CP_COMMIT();
}

__global__ __launch_bounds__(128)
void attn_mma(const __nv_bfloat16* __restrict__ Qhi,
              const __nv_bfloat16* __restrict__ Qlo,
              const __nv_bfloat16* __restrict__ Khi,
              const __nv_bfloat16* __restrict__ Klo,
              const __nv_bfloat16* __restrict__ Vhi,
              const __nv_bfloat16* __restrict__ Vlo,
              __nv_bfloat16* __restrict__ Ohi,
              __nv_bfloat16* __restrict__ Olo)
{
    const uint32_t sb = smem_u32(dynsm);
    const uint32_t stb = sb + QSZ;
    const int tid = threadIdx.x;
    const int lane = tid & 31;
    const int warp = tid >> 5;
    const int qt = blockIdx.x, h = blockIdx.y, b = blockIdx.z;

    const size_t bh = (size_t)(b * H_ + h) * S_ * DK;
    const int row = tid >> 1;
    const int g0  = (tid & 1) * 4;

    // Q tile load (cp.async, one group)
    {
        const size_t e = bh + (size_t)(qt * 64 + row) * DK + g0 * 8;
        const uint32_t st = sb + row * ASTR + g0 * 16;
        #pragma unroll
        for (int j = 0; j < 4; j++) {
            cp16(st + QHI + j*16, Qhi + e + j*8);
            cp16(st + QLO + j*16, Qlo + e + j*8);
        }
    }
    CP_COMMIT();
    attn_issue(0, stb, row, g0, Khi, Klo, Vhi, Vlo, bh);
    CP_WAIT(1);              // Q done (KV0 may be pending)
    __syncthreads();

    // Hoist Q fragments (loop-invariant)
    uint32_t ah[4][4], al[4][4];
    {
        const uint32_t qrow = (warp * 16 + (lane & 15)) * ASTR + (lane >> 4) * 16;
        #pragma unroll
        for (int ks = 0; ks < 4; ++ks) {
            ldsm_x4(ah[ks], sb + QHI + qrow + ks * 32);
            ldsm_x4(al[ks], sb + QLO + qrow + ks * 32);
        }
    }

    float m0 = -1e30f, m1 = -1e30f, l0 = 0.f, l1 = 0.f;
    float o[8][4];
    #pragma unroll
    for (int nf = 0; nf < 8; nf++)
        #pragma unroll
        for (int r = 0; r < 4; r++) o[nf][r] = 0.f;

    const uint32_t kbrow = (lane & 7) * ASTR + ((lane >> 3) & 1) * 16;
    const uint32_t vbrow = (lane & 15) * ASTR;

    for (int kt = 0; kt < S_ / 64; ++kt) {
        CP_WAIT(0);          // KV tile kt complete
        __syncthreads();     // visibility; all warps done compute(kt-1)
        attn_issue(kt + 1, stb, row, g0, Khi, Klo, Vhi, Vlo, bh);

        const uint32_t kb = stb + (kt & 1) * KVSTAGE;

        // scores S[16q x 64k] (3-pass hi/lo)
        float sacc[8][4];
        #pragma unroll
        for (int nf = 0; nf < 8; nf++)
            #pragma unroll
            for (int r = 0; r < 4; r++) sacc[nf][r] = 0.f;

        #pragma unroll
        for (int ks = 0; ks < 4; ++ks) {
            #pragma unroll
            for (int nf = 0; nf < 8; ++nf) {
                uint32_t bh2[2], bl2[2];
                const uint32_t ko = nf * 8 * ASTR + ks * 32 + kbrow;
                ldsm_x2(bh2, kb + AK_HI + ko);
                ldsm_x2(bl2, kb + AK_LO + ko);
                mma16816(sacc[nf], ah[ks], bh2);
                mma16816(sacc[nf], al[ks], bh2);
                mma16816(sacc[nf], ah[ks], bl2);
            }
        }

        // online softmax (exp2 domain; Q pre-scaled by 0.125*log2 e)
        float rm0 = -1e30f, rm1 = -1e30f;
        #pragma unroll
        for (int nf = 0; nf < 8; nf++) {
            rm0 = fmaxf(rm0, fmaxf(sacc[nf][0], sacc[nf][1]));
            rm1 = fmaxf(rm1, fmaxf(sacc[nf][2], sacc[nf][3]));
        }
        rm0 = fmaxf(rm0, __shfl_xor_sync(0xffffffffu, rm0, 1));
        rm0 = fmaxf(rm0, __shfl_xor_sync(0xffffffffu, rm0, 2));
        rm1 = fmaxf(rm1, __shfl_xor_sync(0xffffffffu, rm1, 1));
        rm1 = fmaxf(rm1, __shfl_xor_sync(0xffffffffu, rm1, 2));
        const float mn0 = fmaxf(m0, rm0), mn1 = fmaxf(m1, rm1);
        const float alpha0 = exp2fast(m0 - mn0);
        const float alpha1 = exp2fast(m1 - mn1);
        m0 = mn0; m1 = mn1;

        uint32_t pahi[4][4], palo[4][4];
        float rs0 = 0.f, rs1 = 0.f;
        #pragma unroll
        for (int nf = 0; nf < 8; nf++) {
            float p0 = exp2fast(sacc[nf][0] - mn0);
            float p1 = exp2fast(sacc[nf][1] - mn0);
            float p2 = exp2fast(sacc[nf][2] - mn1);
            float p3 = exp2fast(sacc[nf][3] - mn1);
            rs0 += p0 + p1;
            rs1 += p2 + p3;
            const int ks = nf >> 1, hf = (nf & 1) * 2;
            split2(p0, p1, pahi[ks][hf],     palo[ks][hf]);
            split2(p2, p3, pahi[ks][hf + 1], palo[ks][hf + 1]);
        }
        rs0 += __shfl_xor_sync(0xffffffffu, rs0, 1);
        rs0 += __shfl_xor_sync(0xffffffffu, rs0, 2);
        rs1 += __shfl_xor_sync(0xffffffffu, rs1, 1);
        rs1 += __shfl_xor_sync(0xffffffffu, rs1, 2);
        l0 = l0 * alpha0 + rs0;
        l1 = l1 * alpha1 + rs1;

        #pragma unroll
        for (int nf = 0; nf < 8; nf++) {
            o[nf][0] *= alpha0; o[nf][1] *= alpha0;
            o[nf][2] *= alpha1; o[nf][3] *= alpha1;
        }

        // O += P * V (3-pass hi/lo), V frags via ldmatrix.trans
        #pragma unroll
        for (int ks = 0; ks < 4; ++ks) {
            #pragma unroll
            for (int nf = 0; nf < 8; ++nf) {
                uint32_t bh2[2], bl2[2];
                const uint32_t vo = ks * 16 * ASTR + vbrow + nf * 16;
                ldsm_x2t(bh2, kb + AV_HI + vo);
                ldsm_x2t(bl2, kb + AV_LO + vo);
                mma16816(o[nf], pahi[ks], bh2);
                mma16816(o[nf], palo[ks], bh2);
                mma16816(o[nf], pahi[ks], bl2);
            }
        }
    }

    // epilogue: normalize, split to hi/lo bf16, store merged [B, S, H*Dk]
    const float i0 = 1.0f / l0;
    const float i1 = 1.0f / l1;
    const int r0 = qt * 64 + warp * 16 + (lane >> 2);
    #pragma unroll
    for (int nf = 0; nf < 8; nf++) {
        const int col = h * 64 + nf * 8 + (lane & 3) * 2;
        uint32_t h2, l2;
        split2(o[nf][0] * i0, o[nf][1] * i0, h2, l2);
        const size_t ia = (size_t)(b * S_ + r0) * DM + col;
        *(uint32_t*)(Ohi + ia) = h2;
        *(uint32_t*)(Olo + ia) = l2;
        split2(o[nf][2] * i1, o[nf][3] * i1, h2, l2);
        const size_t ib = (size_t)(b * S_ + r0 + 8) * DM + col;
        *(uint32_t*)(Ohi + ib) = h2;
        *(uint32_t*)(Olo + ib) = l2;
    }
}

// ---------------------------------------------------------------------------
extern "C" void kernel_launch(void* const* d_in, const int* in_sizes, int n_in,
                              void* d_out, int out_size)
{
    const float* q  = (const float*)d_in[0];
    const float* k  = (const float*)d_in[1];
    const float* v  = (const float*)d_in[2];
    const float* Wq = (const float*)d_in[3];
    const float* bq = (const float*)d_in[4];
    const float* Wk = (const float*)d_in[5];
    const float* bk = (const float*)d_in[6];
    const float* Wv = (const float*)d_in[7];
    const float* bv = (const float*)d_in[8];
    const float* Wo = (const float*)d_in[9];
    const float* bo = (const float*)d_in[10];
    float* out = (float*)d_out;

    __nv_bfloat16 *gXhi, *gXlo, *gWhi, *gWlo;
    __nv_bfloat16 *gQhi, *gQlo, *gKhi, *gKlo, *gVhi, *gVlo, *gOhi, *gOlo;
    cudaGetSymbolAddress((void**)&gXhi, g_Xhi);
    cudaGetSymbolAddress((void**)&gXlo, g_Xlo);
    cudaGetSymbolAddress((void**)&gWhi, g_Whi);
    cudaGetSymbolAddress((void**)&gWlo, g_Wlo);
    cudaGetSymbolAddress((void**)&gQhi, g_Qhi);
    cudaGetSymbolAddress((void**)&gQlo, g_Qlo);
    cudaGetSymbolAddress((void**)&gKhi, g_Khi);
    cudaGetSymbolAddress((void**)&gKlo, g_Klo);
    cudaGetSymbolAddress((void**)&gVhi, g_Vhi);
    cudaGetSymbolAddress((void**)&gVlo, g_Vlo);
    cudaGetSymbolAddress((void**)&gOhi, g_Ohi);
    cudaGetSymbolAddress((void**)&gOlo, g_Olo);

    cudaFuncSetAttribute(gemm_bf16,
        cudaFuncAttributeMaxDynamicSharedMemorySize, GEMM_SMEM);
    cudaFuncSetAttribute(attn_mma,
        cudaFuncAttributeMaxDynamicSharedMemorySize, ATTN_SMEM);

    const int WN  = DM * DM;
    const int n4w = WN / 4;
    const int n4a = M_ * DM / 4;
    dim3 wg((n4w + 255) / 256), ag((n4a + 255) / 256);
    dim3 gg(DM / 128, M_ / 128);
    const float SCQ = 0.1803368801f;   // 0.125 * log2(e)

    split_bf16<<<wg, 256>>>(Wq, gWhi + 0*WN, gWlo + 0*WN, n4w);
    split_bf16<<<wg, 256>>>(Wk, gWhi + 1*WN, gWlo + 1*WN, n4w);
    split_bf16<<<wg, 256>>>(Wv, gWhi + 2*WN, gWlo + 2*WN, n4w);
    split_bf16<<<wg, 256>>>(Wo, gWhi + 3*WN, gWlo + 3*WN, n4w);

    split_bf16<<<ag, 256>>>(q, gXhi, gXlo, n4a);
    gemm_bf16<<<gg, 256, GEMM_SMEM>>>(gXhi, gXlo, gWhi + 0*WN, gWlo + 0*WN,
                                      bq, SCQ, gQhi, gQlo, nullptr, 1);
    split_bf16<<<ag, 256>>>(k, gXhi, gXlo, n4a);
    gemm_bf16<<<gg, 256, GEMM_SMEM>>>(gXhi, gXlo, gWhi + 1*WN, gWlo + 1*WN,
                                      bk, 1.0f, gKhi, gKlo, nullptr, 1);
    split_bf16<<<ag, 256>>>(v, gXhi, gXlo, n4a);
    gemm_bf16<<<gg, 256, GEMM_SMEM>>>(gXhi, gXlo, gWhi + 2*WN, gWlo + 2*WN,
                                      bv, 1.0f, gVhi, gVlo, nullptr, 1);

    attn_mma<<<dim3(S_ / 64, H_, B_), 128, ATTN_SMEM>>>(
        gQhi, gQlo, gKhi, gKlo, gVhi, gVlo, gOhi, gOlo);

    gemm_bf16<<<gg, 256, GEMM_SMEM>>>(gOhi, gOlo, gWhi + 3*WN, gWlo + 3*WN,
                                      bo, 1.0f, nullptr, nullptr, out, 0);
}

// round 6
// speedup vs baseline: 1.0831x; 1.0831x over previous
#include <cuda_runtime.h>
#include <cuda_bf16.h>
#include <math_constants.h>
#include <cstdint>

#define B_  4
#define H_  16
#define S_  2048
#define DM  1024
#define DK  64
#define M_  (B_*S_)

// ---------------- scratch (device globals; no allocation allowed) ----------
__device__ float g_Q[M_*DM];
__device__ float g_K[M_*DM];
__device__ float g_V[M_*DM];
__device__ float g_attn[M_*DM];
__device__ __nv_bfloat16 g_Whi[4*DM*DM], g_Wlo[4*DM*DM];

__device__ __forceinline__ uint32_t smem_u32(const void* p) {
    uint32_t a;
    asm("{ .reg .u64 t; cvta.to.shared.u64 t, %1; cvt.u32.u64 %0, t; }"
        : "=r"(a) : "l"(p));
    return a;
}
__device__ __forceinline__ void cp16(uint32_t dst, const void* src) {
    asm volatile("cp.async.cg.shared.global [%0], [%1], 16;"
        :: "r"(dst), "l"(src));
}
#define CP_COMMIT() asm volatile("cp.async.commit_group;" ::: "memory")
#define CP_WAIT(n)  asm volatile("cp.async.wait_group %0;" :: "n"(n) : "memory")

__device__ __forceinline__ void ldsm_x4(uint32_t r[4], uint32_t addr) {
    asm volatile("ldmatrix.sync.aligned.m8n8.x4.shared.b16 {%0,%1,%2,%3}, [%4];"
        : "=r"(r[0]), "=r"(r[1]), "=r"(r[2]), "=r"(r[3]) : "r"(addr));
}
__device__ __forceinline__ void ldsm_x2(uint32_t r[2], uint32_t addr) {
    asm volatile("ldmatrix.sync.aligned.m8n8.x2.shared.b16 {%0,%1}, [%2];"
        : "=r"(r[0]), "=r"(r[1]) : "r"(addr));
}
__device__ __forceinline__ void ldsm_x2t(uint32_t r[2], uint32_t addr) {
    asm volatile("ldmatrix.sync.aligned.m8n8.x2.trans.shared.b16 {%0,%1}, [%2];"
        : "=r"(r[0]), "=r"(r[1]) : "r"(addr));
}
__device__ __forceinline__ void mma16816(float d[4], const uint32_t a[4],
                                         const uint32_t b[2]) {
    asm volatile(
        "mma.sync.aligned.m16n8k16.row.col.f32.bf16.bf16.f32 "
        "{%0,%1,%2,%3}, {%4,%5,%6,%7}, {%8,%9}, {%0,%1,%2,%3};"
        : "+f"(d[0]), "+f"(d[1]), "+f"(d[2]), "+f"(d[3])
        : "r"(a[0]), "r"(a[1]), "r"(a[2]), "r"(a[3]), "r"(b[0]), "r"(b[1]));
}

__device__ __forceinline__ uint32_t pk_bf2(float x, float y) {
    __nv_bfloat162 h = __floats2bfloat162_rn(x, y);
    return *reinterpret_cast<uint32_t*>(&h);
}
__device__ __forceinline__ void split2(float x, float y,
                                       uint32_t& hi, uint32_t& lo) {
    __nv_bfloat162 h2 = __floats2bfloat162_rn(x, y);
    float2 hf = __bfloat1622float2(h2);
    __nv_bfloat162 l2 = __floats2bfloat162_rn(x - hf.x, y - hf.y);
    hi = *reinterpret_cast<uint32_t*>(&h2);
    lo = *reinterpret_cast<uint32_t*>(&l2);
}
__device__ __forceinline__ void split8(float4 v0, float4 v1,
                                       uint4& hi, uint4& lo) {
    float h[8], f[8] = {v0.x, v0.y, v0.z, v0.w, v1.x, v1.y, v1.z, v1.w};
    float l[8];
    #pragma unroll
    for (int i = 0; i < 8; i++) {
        __nv_bfloat16 hb = __float2bfloat16_rn(f[i]);
        h[i] = __bfloat162float(hb);
        l[i] = f[i] - h[i];
    }
    hi = make_uint4(pk_bf2(h[0],h[1]), pk_bf2(h[2],h[3]),
                    pk_bf2(h[4],h[5]), pk_bf2(h[6],h[7]));
    lo = make_uint4(pk_bf2(l[0],l[1]), pk_bf2(l[2],l[3]),
                    pk_bf2(l[4],l[5]), pk_bf2(l[6],l[7]));
}

// Fast exp2 on FMA pipe (no MUFU).
__device__ __forceinline__ float exp2fast(float x) {
    x = fmaxf(x, -126.0f);
    float z = x + 12582912.0f;
    int   k = __float_as_int(z) - 0x4B400000;
    float f = x - (z - 12582912.0f);
    float p = fmaf(0.00133336f, f, 0.00961813f);
    p = fmaf(p, f, 0.05550411f);
    p = fmaf(p, f, 0.24022651f);
    p = fmaf(p, f, 0.69314718f);
    p = fmaf(p, f, 1.0f);
    return __int_as_float(__float_as_int(p) + (k << 23));
}

// ---------------------------------------------------------------------------
// fp32 -> bf16 hi/lo split (weights only; ~2 MB each, ~3 us)
// ---------------------------------------------------------------------------
__global__ __launch_bounds__(256)
void split_bf16(const float* __restrict__ x,
                __nv_bfloat16* __restrict__ hi,
                __nv_bfloat16* __restrict__ lo, int n4)
{
    int i = blockIdx.x * blockDim.x + threadIdx.x;
    if (i >= n4) return;
    float4 v = reinterpret_cast<const float4*>(x)[i];
    uint32_t h0, l0, h1, l1;
    split2(v.x, v.y, h0, l0);
    split2(v.z, v.w, h1, l1);
    reinterpret_cast<uint2*>(hi)[i] = make_uint2(h0, h1);
    reinterpret_cast<uint2*>(lo)[i] = make_uint2(l0, l1);
}

// ---------------------------------------------------------------------------
// GEMM: out[m,n] = sum_k A[m,k]*W[n,k] + bias[n]
//  A: fp32, split in-kernel (2-stage smem buffer, 1 sync/chunk)
//  W: pre-split bf16 hi/lo via cp.async (4-stage)
//  3-pass fp32 emulation: Ahi*Whi + Alo*Whi + Ahi*Wlo
// CTA 128x128, BK=32, 8 warps (2x4), warp tile 64x32; 80B row stride.
// ---------------------------------------------------------------------------
#define GTSTR   80
#define GTILE   (128*GTSTR)            // 10240 B
#define A_BASE  0                      // 2 stages x (hi,lo) = 40960
#define W_BASE  (4*GTILE)              // 4 stages x (hi,lo) = 81920
#define GEMM_SMEM (12*GTILE)           // 122880

extern __shared__ char dynsm[];

__device__ __forceinline__ void w_issue(
    int c, uint32_t sb, int row, int half,
    const __nv_bfloat16* Whi, const __nv_bfloat16* Wlo, size_t woff)
{
    if (c < DM / 32) {
        const uint32_t st = sb + W_BASE + (c & 3) * (2*GTILE)
                          + row * GTSTR + half * 32;
        const size_t e = woff + c * 32 + half * 16;
        cp16(st,          Whi + e);  cp16(st + 16,          Whi + e + 8);
        cp16(st + GTILE,  Wlo + e);  cp16(st + GTILE + 16,  Wlo + e + 8);
    }
    CP_COMMIT();
}

__global__ __launch_bounds__(256, 1)
void gemm_v2(const float* __restrict__ A,
             const __nv_bfloat16* __restrict__ Whi,
             const __nv_bfloat16* __restrict__ Wlo,
             const float* __restrict__ bias, float* __restrict__ out,
             int split_heads)
{
    const uint32_t sb = smem_u32(dynsm);
    const int tid = threadIdx.x;
    const int m0  = blockIdx.y << 7;
    const int n0  = blockIdx.x << 7;
    const int warp = tid >> 5;
    const int lane = tid & 31;
    const int wm = (warp >> 2) * 64;
    const int wn = (warp & 3) * 32;

    const uint32_t arow = (lane & 15) * GTSTR + (lane >> 4) * 16;
    const uint32_t brow = (lane & 7) * GTSTR + ((lane >> 3) & 1) * 16;

    const int lrow = tid >> 1;
    const int half = tid & 1;
    const float* Ag = A + (size_t)(m0 + lrow) * DM + half * 16;
    const size_t woff = (size_t)(n0 + lrow) * DM;
    const uint32_t asm_off = lrow * GTSTR + half * 32;   // A smem byte offset

    float acc[4][4][4];
    #pragma unroll
    for (int i = 0; i < 4; i++)
        #pragma unroll
        for (int j = 0; j < 4; j++)
            #pragma unroll
            for (int r = 0; r < 4; r++) acc[i][j][r] = 0.f;

    // prologue: W stages 0..2; A(0) split-store buf0; A(1) regs
    w_issue(0, sb, lrow, half, Whi, Wlo, woff);
    w_issue(1, sb, lrow, half, Whi, Wlo, woff);
    w_issue(2, sb, lrow, half, Whi, Wlo, woff);

    float4 a0 = *(const float4*)(Ag);     float4 a1 = *(const float4*)(Ag + 4);
    float4 a2 = *(const float4*)(Ag + 8); float4 a3 = *(const float4*)(Ag + 12);
    {
        uint4 hi, lo;
        char* s = dynsm + A_BASE + asm_off;
        split8(a0, a1, hi, lo);
        *(uint4*)(s)               = hi;  *(uint4*)(s + GTILE)      = lo;
        split8(a2, a3, hi, lo);
        *(uint4*)(s + 16)          = hi;  *(uint4*)(s + GTILE + 16) = lo;
    }
    a0 = *(const float4*)(Ag + 32);  a1 = *(const float4*)(Ag + 36);
    a2 = *(const float4*)(Ag + 40);  a3 = *(const float4*)(Ag + 44);

    for (int c = 0; c < DM / 32; ++c) {
        CP_WAIT(2);            // W stage c complete (per-thread)
        __syncthreads();       // all compute(c-1) done; all stores visible
        w_issue(c + 3, sb, lrow, half, Whi, Wlo, woff);

        if (c + 1 < DM / 32) {      // split-store A(c+1) into alt buffer
            uint4 hi, lo;
            char* s = dynsm + A_BASE + ((c + 1) & 1) * (2*GTILE) + asm_off;
            split8(a0, a1, hi, lo);
            *(uint4*)(s)      = hi;  *(uint4*)(s + GTILE)      = lo;
            split8(a2, a3, hi, lo);
            *(uint4*)(s + 16) = hi;  *(uint4*)(s + GTILE + 16) = lo;
            if (c + 2 < DM / 32) {  // prefetch A(c+2) to regs
                const float* An = Ag + (c + 2) * 32;
                a0 = *(const float4*)(An);      a1 = *(const float4*)(An + 4);
                a2 = *(const float4*)(An + 8);  a3 = *(const float4*)(An + 12);
            }
        }

        const uint32_t ab = sb + A_BASE + (c & 1) * (2*GTILE);
        const uint32_t wb = sb + W_BASE + (c & 3) * (2*GTILE);
        #pragma unroll
        for (int pass = 0; pass < 3; ++pass) {
            const uint32_t aoffs = ab + ((pass == 1) ? GTILE : 0);
            const uint32_t boffs = wb + ((pass == 2) ? GTILE : 0);
            #pragma unroll
            for (int ks = 0; ks < 2; ++ks) {
                uint32_t af[4][4], bf[4][2];
                #pragma unroll
                for (int mt = 0; mt < 4; ++mt)
                    ldsm_x4(af[mt], aoffs + (wm + mt*16) * GTSTR + ks*32 + arow);
                #pragma unroll
                for (int nt = 0; nt < 4; ++nt)
                    ldsm_x2(bf[nt], boffs + (wn + nt*8) * GTSTR + ks*32 + brow);
                #pragma unroll
                for (int mt = 0; mt < 4; ++mt)
                    #pragma unroll
                    for (int nt = 0; nt < 4; ++nt)
                        mma16816(acc[mt][nt], af[mt], bf[nt]);
            }
        }
    }

    #pragma unroll
    for (int mt = 0; mt < 4; ++mt) {
        #pragma unroll
        for (int nt = 0; nt < 4; ++nt) {
            const int col = n0 + wn + nt*8 + (lane & 3) * 2;
            const float2 bv = *(const float2*)(bias + col);
            #pragma unroll
            for (int hf = 0; hf < 2; ++hf) {
                const int row = m0 + wm + mt*16 + (lane >> 2) + hf * 8;
                float2 o2 = make_float2(acc[mt][nt][2*hf]   + bv.x,
                                        acc[mt][nt][2*hf+1] + bv.y);
                size_t idx;
                if (split_heads) {
                    const int head = col >> 6;
                    const int bi = row >> 11, si = row & (S_ - 1);
                    idx = (((size_t)(bi * H_ + head)) * S_ + si) * DK + (col & 63);
                } else {
                    idx = (size_t)row * DM + col;
                }
                *(float2*)(out + idx) = o2;
            }
        }
    }
}

// ---------------------------------------------------------------------------
// Tensor-core flash attention (R4 verbatim — verified 734us).
// CTA: 128 q-rows of one (b,h); 8 warps x 16 q-rows; key tiles of 64.
// ---------------------------------------------------------------------------
#define ASTR   144
#define A_QHI  0
#define A_QLO  18432
#define A_KHI  36864
#define A_KLO  46080
#define A_VHI  55296
#define A_VLO  64512
#define ATTN_SMEM 73728

__global__ __launch_bounds__(256, 1)
void attn_mma(const float* __restrict__ Qh, const float* __restrict__ Kh,
              const float* __restrict__ Vh, float* __restrict__ outA)
{
    const uint32_t sb = smem_u32(dynsm);
    const int tid = threadIdx.x;
    const int lane = tid & 31;
    const int warp = tid >> 5;
    const int qt = blockIdx.x, h = blockIdx.y, b = blockIdx.z;

    const size_t bh = (size_t)(b * H_ + h) * S_ * DK;
    const float* Qb = Qh + bh + (size_t)qt * 128 * DK;
    const float* Kb = Kh + bh;
    const float* Vb = Vh + bh;

    {
        const int row = tid >> 1;
        const int c0  = (tid & 1) * 32;
        const float* g = Qb + row * DK + c0;
        char* s = dynsm + row * ASTR + c0 * 2;
        const float sc = 0.1803368801f;     // 0.125 * log2(e)
        #pragma unroll
        for (int j = 0; j < 4; j++) {
            float4 v0 = *(const float4*)(g + j*8);
            float4 v1 = *(const float4*)(g + j*8 + 4);
            v0.x *= sc; v0.y *= sc; v0.z *= sc; v0.w *= sc;
            v1.x *= sc; v1.y *= sc; v1.z *= sc; v1.w *= sc;
            uint4 hi, lo; split8(v0, v1, hi, lo);
            *(uint4*)(s + A_QHI + j*16) = hi;
            *(uint4*)(s + A_QLO + j*16) = lo;
        }
    }

    float m0 = -1e30f, m1 = -1e30f, l0 = 0.f, l1 = 0.f;
    float o[8][4];
    #pragma unroll
    for (int nf = 0; nf < 8; nf++)
        #pragma unroll
        for (int r = 0; r < 4; r++) o[nf][r] = 0.f;

    const int krow = tid >> 2;
    const int kcg  = (tid & 3) * 16;
    char* kvs = dynsm + krow * ASTR + kcg * 2;

    float4 kf[4], vf[4];
    {
        const float* kg = Kb + (size_t)krow * DK + kcg;
        const float* vg = Vb + (size_t)krow * DK + kcg;
        #pragma unroll
        for (int j = 0; j < 4; j++) {
            kf[j] = *(const float4*)(kg + j*4);
            vf[j] = *(const float4*)(vg + j*4);
        }
    }

    const uint32_t qrow = (warp * 16 + (lane & 15)) * ASTR + (lane >> 4) * 16;
    const uint32_t kbrow = (lane & 7) * ASTR + ((lane >> 3) & 1) * 16;
    const uint32_t vbrow = (lane & 15) * ASTR;

    for (int kt = 0; kt < S_ / 64; ++kt) {
        __syncthreads();
        {
            uint4 hi, lo;
            split8(kf[0], kf[1], hi, lo);
            *(uint4*)(kvs + A_KHI)      = hi;  *(uint4*)(kvs + A_KLO)      = lo;
            split8(kf[2], kf[3], hi, lo);
            *(uint4*)(kvs + A_KHI + 16) = hi;  *(uint4*)(kvs + A_KLO + 16) = lo;
            split8(vf[0], vf[1], hi, lo);
            *(uint4*)(kvs + A_VHI)      = hi;  *(uint4*)(kvs + A_VLO)      = lo;
            split8(vf[2], vf[3], hi, lo);
            *(uint4*)(kvs + A_VHI + 16) = hi;  *(uint4*)(kvs + A_VLO + 16) = lo;
        }
        __syncthreads();

        if (kt < S_ / 64 - 1) {
            const float* kg = Kb + (size_t)((kt+1)*64 + krow) * DK + kcg;
            const float* vg = Vb + (size_t)((kt+1)*64 + krow) * DK + kcg;
            #pragma unroll
            for (int j = 0; j < 4; j++) {
                kf[j] = *(const float4*)(kg + j*4);
                vf[j] = *(const float4*)(vg + j*4);
            }
        }

        float sacc[8][4];
        #pragma unroll
        for (int nf = 0; nf < 8; nf++)
            #pragma unroll
            for (int r = 0; r < 4; r++) sacc[nf][r] = 0.f;

        #pragma unroll
        for (int ks = 0; ks < 4; ++ks) {
            uint32_t ah[4], al[4];
            ldsm_x4(ah, sb + A_QHI + qrow + ks * 32);
            ldsm_x4(al, sb + A_QLO + qrow + ks * 32);
            #pragma unroll
            for (int nf = 0; nf < 8; ++nf) {
                uint32_t bh2[2], bl2[2];
                const uint32_t ko = nf * 8 * ASTR + ks * 32 + kbrow;
                ldsm_x2(bh2, sb + A_KHI + ko);
                ldsm_x2(bl2, sb + A_KLO + ko);
                mma16816(sacc[nf], ah, bh2);
                mma16816(sacc[nf], al, bh2);
                mma16816(sacc[nf], ah, bl2);
            }
        }

        float rm0 = -1e30f, rm1 = -1e30f;
        #pragma unroll
        for (int nf = 0; nf < 8; nf++) {
            rm0 = fmaxf(rm0, fmaxf(sacc[nf][0], sacc[nf][1]));
            rm1 = fmaxf(rm1, fmaxf(sacc[nf][2], sacc[nf][3]));
        }
        rm0 = fmaxf(rm0, __shfl_xor_sync(0xffffffffu, rm0, 1));
        rm0 = fmaxf(rm0, __shfl_xor_sync(0xffffffffu, rm0, 2));
        rm1 = fmaxf(rm1, __shfl_xor_sync(0xffffffffu, rm1, 1));
        rm1 = fmaxf(rm1, __shfl_xor_sync(0xffffffffu, rm1, 2));
        const float mn0 = fmaxf(m0, rm0), mn1 = fmaxf(m1, rm1);
        const float alpha0 = exp2fast(m0 - mn0);
        const float alpha1 = exp2fast(m1 - mn1);
        m0 = mn0; m1 = mn1;

        uint32_t pahi[4][4], palo[4][4];
        float rs0 = 0.f, rs1 = 0.f;
        #pragma unroll
        for (int nf = 0; nf < 8; nf++) {
            float p0 = exp2fast(sacc[nf][0] - mn0);
            float p1 = exp2fast(sacc[nf][1] - mn0);
            float p2 = exp2fast(sacc[nf][2] - mn1);
            float p3 = exp2fast(sacc[nf][3] - mn1);
            rs0 += p0 + p1;
            rs1 += p2 + p3;
            const int ks = nf >> 1, hf = (nf & 1) * 2;
            split2(p0, p1, pahi[ks][hf],     palo[ks][hf]);
            split2(p2, p3, pahi[ks][hf + 1], palo[ks][hf + 1]);
        }
        rs0 += __shfl_xor_sync(0xffffffffu, rs0, 1);
        rs0 += __shfl_xor_sync(0xffffffffu, rs0, 2);
        rs1 += __shfl_xor_sync(0xffffffffu, rs1, 1);
        rs1 += __shfl_xor_sync(0xffffffffu, rs1, 2);
        l0 = l0 * alpha0 + rs0;
        l1 = l1 * alpha1 + rs1;

        #pragma unroll
        for (int nf = 0; nf < 8; nf++) {
            o[nf][0] *= alpha0; o[nf][1] *= alpha0;
            o[nf][2] *= alpha1; o[nf][3] *= alpha1;
        }

        #pragma unroll
        for (int ks = 0; ks < 4; ++ks) {
            #pragma unroll
            for (int nf = 0; nf < 8; ++nf) {
                uint32_t bh2[2], bl2[2];
                const uint32_t vo = ks * 16 * ASTR + vbrow + nf * 16;
                ldsm_x2t(bh2, sb + A_VHI + vo);
                ldsm_x2t(bl2, sb + A_VLO + vo);
                mma16816(o[nf], pahi[ks], bh2);
                mma16816(o[nf], palo[ks], bh2);
                mma16816(o[nf], pahi[ks], bl2);
            }
        }
    }

    const float i0 = 1.0f / l0;
    const float i1 = 1.0f / l1;
    const int r0 = qt * 128 + warp * 16 + (lane >> 2);
    #pragma unroll
    for (int nf = 0; nf < 8; nf++) {
        const int col = h * 64 + nf * 8 + (lane & 3) * 2;
        *(float2*)(outA + (size_t)(b * S_ + r0) * DM + col) =
            make_float2(o[nf][0] * i0, o[nf][1] * i0);
        *(float2*)(outA + (size_t)(b * S_ + r0 + 8) * DM + col) =
            make_float2(o[nf][2] * i1, o[nf][3] * i1);
    }
}

// ---------------------------------------------------------------------------
extern "C" void kernel_launch(void* const* d_in, const int* in_sizes, int n_in,
                              void* d_out, int out_size)
{
    const float* q  = (const float*)d_in[0];
    const float* k  = (const float*)d_in[1];
    const float* v  = (const float*)d_in[2];
    const float* Wq = (const float*)d_in[3];
    const float* bq = (const float*)d_in[4];
    const float* Wk = (const float*)d_in[5];
    const float* bk = (const float*)d_in[6];
    const float* Wv = (const float*)d_in[7];
    const float* bv = (const float*)d_in[8];
    const float* Wo = (const float*)d_in[9];
    const float* bo = (const float*)d_in[10];
    float* out = (float*)d_out;

    float *gQ, *gK, *gV, *gA;
    __nv_bfloat16 *gWhi, *gWlo;
    cudaGetSymbolAddress((void**)&gQ,   g_Q);
    cudaGetSymbolAddress((void**)&gK,   g_K);
    cudaGetSymbolAddress((void**)&gV,   g_V);
    cudaGetSymbolAddress((void**)&gA,   g_attn);
    cudaGetSymbolAddress((void**)&gWhi, g_Whi);
    cudaGetSymbolAddress((void**)&gWlo, g_Wlo);

    cudaFuncSetAttribute(gemm_v2,
        cudaFuncAttributeMaxDynamicSharedMemorySize, GEMM_SMEM);
    cudaFuncSetAttribute(attn_mma,
        cudaFuncAttributeMaxDynamicSharedMemorySize, ATTN_SMEM);

    const int WN  = DM * DM;
    const int n4w = WN / 4;
    dim3 wg((n4w + 255) / 256);
    dim3 gg(DM / 128, M_ / 128);   // (8, 64)

    split_bf16<<<wg, 256>>>(Wq, gWhi + 0*WN, gWlo + 0*WN, n4w);
    split_bf16<<<wg, 256>>>(Wk, gWhi + 1*WN, gWlo + 1*WN, n4w);
    split_bf16<<<wg, 256>>>(Wv, gWhi + 2*WN, gWlo + 2*WN, n4w);
    split_bf16<<<wg, 256>>>(Wo, gWhi + 3*WN, gWlo + 3*WN, n4w);

    gemm_v2<<<gg, 256, GEMM_SMEM>>>(q, gWhi + 0*WN, gWlo + 0*WN, bq, gQ, 1);
    gemm_v2<<<gg, 256, GEMM_SMEM>>>(k, gWhi + 1*WN, gWlo + 1*WN, bk, gK, 1);
    gemm_v2<<<gg, 256, GEMM_SMEM>>>(v, gWhi + 2*WN, gWlo + 2*WN, bv, gV, 1);
    attn_mma<<<dim3(S_ / 128, H_, B_), 256, ATTN_SMEM>>>(gQ, gK, gV, gA);
    gemm_v2<<<gg, 256, GEMM_SMEM>>>(gA, gWhi + 3*WN, gWlo + 3*WN, bo, out, 0);
}